// round 4
// baseline (speedup 1.0000x reference)
#include <cuda_runtime.h>
#include <cstdint>

// DETRMatcher: reference's softmax/cdist/argmin are dead code w.r.t. outputs.
// Output = 8.1M float32:
//   [0, 1.62M)      : 0.0f           (two int32 zero index tensors)
//   [1.62M, 4.86M)  : outputs_coord  (bitwise copy, 3.24M f32)
//   [4.86M, 8.10M)  : target_boxes   (bitwise copy, 3.24M f32)
//
// R2/R3: SM copy kernel plateaued at ~10.4us (~5.6 TB/s combined L2) across
// two very different launch shapes -> LTS-path ceiling, not latency/issue.
// R4 experiment: route the work through memset/memcpy graph nodes (copy-engine
// backed when possible) instead of SM LDG/STG. All three calls are async,
// graph-capturable, and allocation-free.

static constexpr size_t N_ZERO  = 2ull * 900 * 900;       // 1,620,000 elems
static constexpr size_t N_COORD = 900ull * 900 * 4;       // 3,240,000 elems

static constexpr size_t B_ZERO  = N_ZERO  * sizeof(float); //  6,480,000 B
static constexpr size_t B_COORD = N_COORD * sizeof(float); // 12,960,000 B

extern "C" void kernel_launch(void* const* d_in, const int* in_sizes, int n_in,
                              void* d_out, int out_size)
{
    // metadata order: outputs_class, outputs_coord, target_classes, target_boxes
    const void* coord = d_in[1];
    const void* boxes = d_in[3];
    char* out = (char*)d_out;

    cudaMemsetAsync(out, 0, B_ZERO);
    cudaMemcpyAsync(out + B_ZERO,           coord, B_COORD,
                    cudaMemcpyDeviceToDevice);
    cudaMemcpyAsync(out + B_ZERO + B_COORD, boxes, B_COORD,
                    cudaMemcpyDeviceToDevice);
}

// round 6
// speedup vs baseline: 2.1463x; 2.1463x over previous
#include <cuda_runtime.h>

// DETRMatcher: reference's softmax/cdist/argmin are dead code w.r.t. outputs
// (scatter of 0 into zeros = zeros). Output = 8.1M float32:
//   [0, 1.62M)      : 0.0f           (two int32 zero index tensors)
//   [1.62M, 4.86M)  : outputs_coord  (bitwise copy)
//   [4.86M, 8.10M)  : target_boxes   (bitwise copy)
//
// R4 (memset+memcpy nodes) regressed to 23us -> SM kernel path is right.
// R5: single-wave persistent layout — 148x8 = 1184 blocks, each owning a
// contiguous chunk (no partial second wave, better L2 locality), inner loop
// unrolled x4 with front-batched 16B loads.

static constexpr int V_ZERO  = 405000;                 // float4 slots of zeros
static constexpr int V_COORD = 810000;                 // float4 slots per copy
static constexpr int V_TOTAL = V_ZERO + 2 * V_COORD;   // 2,025,000

static constexpr int TPB    = 256;
static constexpr int BLOCKS = 148 * 8;                 // exactly one wave at occ=8
static constexpr int CHUNK  = (V_TOTAL + BLOCKS - 1) / BLOCKS;  // 1711

__device__ __forceinline__ float4 seg_value(int j,
                                            const float4* __restrict__ coord,
                                            const float4* __restrict__ boxes)
{
    if (j >= V_ZERO + V_COORD) return boxes[j - (V_ZERO + V_COORD)];
    if (j >= V_ZERO)           return coord[j - V_ZERO];
    return make_float4(0.f, 0.f, 0.f, 0.f);
}

__global__ void __launch_bounds__(TPB)
detr_matcher_pack_f32(const float4* __restrict__ coord,
                      const float4* __restrict__ boxes,
                      float4* __restrict__ out)
{
    const int start = blockIdx.x * CHUNK;
    const int end   = min(start + CHUNK, V_TOTAL);

    int j = start + threadIdx.x;

    // Unrolled x4, loads front-batched ahead of stores (MLP ~4).
    for (; j + 3 * TPB < end; j += 4 * TPB) {
        float4 v0 = seg_value(j,           coord, boxes);
        float4 v1 = seg_value(j +     TPB, coord, boxes);
        float4 v2 = seg_value(j + 2 * TPB, coord, boxes);
        float4 v3 = seg_value(j + 3 * TPB, coord, boxes);
        out[j]           = v0;
        out[j +     TPB] = v1;
        out[j + 2 * TPB] = v2;
        out[j + 3 * TPB] = v3;
    }
    for (; j < end; j += TPB)
        out[j] = seg_value(j, coord, boxes);
}

extern "C" void kernel_launch(void* const* d_in, const int* in_sizes, int n_in,
                              void* d_out, int out_size)
{
    // metadata order: outputs_class, outputs_coord, target_classes, target_boxes
    const float4* coord = (const float4*)d_in[1];
    const float4* boxes = (const float4*)d_in[3];
    float4* out = (float4*)d_out;

    detr_matcher_pack_f32<<<BLOCKS, TPB>>>(coord, boxes, out);
}